// round 5
// baseline (speedup 1.0000x reference)
#include <cuda_runtime.h>
#include <cstdint>
#include <cstddef>

#define FULLMASK 0xffffffffu
#define B_ROWS 65536
#define D_INN 1408
#define P_DIM 256
#define N_CODE 64
#define KC 32
#define NCHUNK (D_INN / KC)   // 44
#define MT 64
#define NTHREADS 512

// ---- shared memory layout (float offsets) ----
#define SB_B     0        // bias [256]
#define SB_G     256      // gamma [256]
#define SB_BE    512      // beta [256]
#define SB_NRM   768      // row norm^2 [64]
#define SB_ZZ    832      // sum z*z per row [64]
#define SB_LOSS  896      // loss accumulator [1]
#define SB_CBT   1024     // codebook transposed [256][64]
#define SB_UNION (1024 + 16384)                     // union: stages OR z rows
#define AS_OFF(bf) (SB_UNION + (bf) * 2048)         // A stage [2][64][32]
#define BS_OFF(bf) (SB_UNION + 4096 + (bf) * 8192)  // B stage [2][32][256]
#define ZS_OFF   SB_UNION                           // z rows [64][256]
#define SMEM_FLOATS (SB_UNION + 20480)              // 37888
#define SMEM_BYTES  (SMEM_FLOATS * 4)               // 151552 B

#define IDX_OFF  ((size_t)B_ROWS * P_DIM)
#define LOSS_OFF (IDX_OFF + B_ROWS)

__device__ float g_cbn2[N_CODE];

static __device__ __forceinline__ void cp16(float* s, const float* g) {
    unsigned sa = (unsigned)__cvta_generic_to_shared(s);
    asm volatile("cp.async.cg.shared.global [%0], [%1], 16;\n" :: "r"(sa), "l"(g));
}

static __device__ __forceinline__ unsigned long long packdup(float x) {
    unsigned long long d;
    unsigned xi = __float_as_uint(x);
    asm("mov.b64 %0, {%1, %2};" : "=l"(d) : "r"(xi), "r"(xi));
    return d;
}

static __device__ __forceinline__ unsigned long long fma2(unsigned long long a,
                                                          unsigned long long b,
                                                          unsigned long long c) {
    unsigned long long d;
    asm("fma.rn.f32x2 %0, %1, %2, %3;" : "=l"(d) : "l"(a), "l"(b), "l"(c));
    return d;
}

static __device__ __forceinline__ unsigned long long add2(unsigned long long a,
                                                          unsigned long long b) {
    unsigned long long d;
    asm("add.rn.f32x2 %0, %1, %2;" : "=l"(d) : "l"(a), "l"(b));
    return d;
}

static __device__ __forceinline__ float wred(float v) {
    #pragma unroll
    for (int o = 16; o; o >>= 1) v += __shfl_xor_sync(FULLMASK, v, o);
    return v;
}

__global__ void init_kernel(const float* __restrict__ cb, float* __restrict__ out, int out_size) {
    int k = threadIdx.x;
    if (k < N_CODE) {
        const float* r = cb + k * P_DIM;
        double s = 0.0;
        #pragma unroll 8
        for (int c = 0; c < P_DIM; ++c) {
            double v = (double)r[c];
            s += v * v;
        }
        g_cbn2[k] = (float)s;
    }
    if (k == 0 && (size_t)out_size > LOSS_OFF) out[LOSS_OFF] = 0.f;
}

__global__ void __launch_bounds__(NTHREADS, 1)
main_kernel(const float* __restrict__ zf, const float* __restrict__ Wm,
            const float* __restrict__ bb, const float* __restrict__ gg,
            const float* __restrict__ be, const float* __restrict__ cb,
            float* __restrict__ out, int out_size) {
    extern __shared__ float sm[];
    const int tid = threadIdx.x;
    const int tm = tid >> 5;   // warp id (0..15); rows tm + 16*i, i<4
    const int tn = tid & 31;   // lane = N-group
    const int rowbase = blockIdx.x * MT;
    const bool aux = (size_t)out_size > LOSS_OFF;

    // ---- prefetch chunk 0 (cp.async) ----
    {
        {   // A: 64x32 floats = 512 float4, one per thread
            int row = tid >> 3, k4 = tid & 7;
            cp16(&sm[AS_OFF(0) + row * KC + k4 * 4],
                 zf + (size_t)(rowbase + row) * D_INN + k4 * 4);
        }
        #pragma unroll
        for (int t = 0; t < 4; ++t) {   // B: 32x256 floats = 2048 float4
            int idx = tid + t * NTHREADS;
            int kk = idx >> 6, c4 = idx & 63;
            cp16(&sm[BS_OFF(0) + kk * P_DIM + c4 * 4],
                 Wm + (size_t)kk * P_DIM + c4 * 4);
        }
        asm volatile("cp.async.commit_group;\n");
    }

    // ---- params + transposed codebook + loss init ----
    if (tid < P_DIM) {
        sm[SB_B + tid]  = bb[tid];
        sm[SB_G + tid]  = gg[tid];
        sm[SB_BE + tid] = be[tid];
    }
    if (tid == 0) sm[SB_LOSS] = 0.f;
    #pragma unroll
    for (int t = 0; t < (N_CODE * P_DIM) / NTHREADS; ++t) {
        int i = tid + t * NTHREADS;
        int k = i >> 8, c = i & 255;
        sm[SB_CBT + c * N_CODE + k] = cb[i];
    }

    // ---- row L2 norms (8 lanes per row; scale-invariant downstream) ----
    {
        int r = tid >> 3, q = tid & 7;
        const float4* z4 = (const float4*)zf;
        size_t base = (size_t)(rowbase + r) * (D_INN / 4) + q;
        float s = 0.f;
        #pragma unroll 4
        for (int t = 0; t < D_INN / 32; ++t) {
            float4 v = z4[base + 8 * t];
            s += v.x * v.x + v.y * v.y + v.z * v.z + v.w * v.w;
        }
        s += __shfl_xor_sync(FULLMASK, s, 1);
        s += __shfl_xor_sync(FULLMASK, s, 2);
        s += __shfl_xor_sync(FULLMASK, s, 4);
        if (q == 0) sm[SB_NRM + r] = s;
    }

    // ---- main GEMM: 64x256 tile; chunk-local accumulation, two-way master fold ----
    unsigned long long acc0[4][4], acc1[4][4];
    #pragma unroll
    for (int i = 0; i < 4; ++i)
        #pragma unroll
        for (int j = 0; j < 4; ++j) { acc0[i][j] = 0ull; acc1[i][j] = 0ull; }

    for (int c = 0; c < NCHUNK; ++c) {
        int bf = c & 1;
        if (c + 1 < NCHUNK) {
            int nb = bf ^ 1;
            {
                int row = tid >> 3, k4 = tid & 7;
                cp16(&sm[AS_OFF(nb) + row * KC + k4 * 4],
                     zf + (size_t)(rowbase + row) * D_INN + (c + 1) * KC + k4 * 4);
            }
            #pragma unroll
            for (int t = 0; t < 4; ++t) {
                int idx = tid + t * NTHREADS;
                int kk = idx >> 6, c4 = idx & 63;
                cp16(&sm[BS_OFF(nb) + kk * P_DIM + c4 * 4],
                     Wm + (size_t)((c + 1) * KC + kk) * P_DIM + c4 * 4);
            }
            asm volatile("cp.async.commit_group;\n");
            asm volatile("cp.async.wait_group 1;\n");
        } else {
            asm volatile("cp.async.wait_group 0;\n");
        }
        __syncthreads();

        const float* As = &sm[AS_OFF(bf)];
        const float* Bs = &sm[BS_OFF(bf)];

        unsigned long long cacc[4][4];
        #pragma unroll
        for (int i = 0; i < 4; ++i)
            #pragma unroll
            for (int j = 0; j < 4; ++j) cacc[i][j] = 0ull;

        #pragma unroll
        for (int kk4 = 0; kk4 < KC / 4; ++kk4) {
            float4 a4[4];
            #pragma unroll
            for (int i = 0; i < 4; ++i)
                a4[i] = *(const float4*)&As[(tm + 16 * i) * KC + kk4 * 4];
            #pragma unroll
            for (int q = 0; q < 4; ++q) {
                const float* brow = &Bs[(kk4 * 4 + q) * P_DIM];
                unsigned long long bw0 = *(const unsigned long long*)&brow[2 * tn];
                unsigned long long bw1 = *(const unsigned long long*)&brow[64 + 2 * tn];
                unsigned long long bw2 = *(const unsigned long long*)&brow[128 + 2 * tn];
                unsigned long long bw3 = *(const unsigned long long*)&brow[192 + 2 * tn];
                #pragma unroll
                for (int i = 0; i < 4; ++i) {
                    float av = ((const float*)&a4[i])[q];
                    unsigned long long aa = packdup(av);
                    cacc[i][0] = fma2(aa, bw0, cacc[i][0]);
                    cacc[i][1] = fma2(aa, bw1, cacc[i][1]);
                    cacc[i][2] = fma2(aa, bw2, cacc[i][2]);
                    cacc[i][3] = fma2(aa, bw3, cacc[i][3]);
                }
            }
        }
        if (bf == 0) {
            #pragma unroll
            for (int i = 0; i < 4; ++i)
                #pragma unroll
                for (int j = 0; j < 4; ++j) acc0[i][j] = add2(acc0[i][j], cacc[i][j]);
        } else {
            #pragma unroll
            for (int i = 0; i < 4; ++i)
                #pragma unroll
                for (int j = 0; j < 4; ++j) acc1[i][j] = add2(acc1[i][j], cacc[i][j]);
        }
        __syncthreads();
    }
    // final fold of the two alternating masters
    #pragma unroll
    for (int i = 0; i < 4; ++i)
        #pragma unroll
        for (int j = 0; j < 4; ++j) acc0[i][j] = add2(acc0[i][j], acc1[i][j]);

    // ---- epilogue: h = g/||x|| + b ; LayerNorm ; l2norm ; write z + zz ----
    #pragma unroll
    for (int i = 0; i < 4; ++i) {
        int lrow = tm + 16 * i;
        float n2 = sm[SB_NRM + lrow];
        float invn = 1.0f / fmaxf(sqrtf(n2), 1e-12f);
        float hv[8];
        #pragma unroll
        for (int jp = 0; jp < 4; ++jp) {
            int c0 = 2 * tn + 64 * jp;
            float lo = __uint_as_float((unsigned)(acc0[i][jp] & 0xffffffffull));
            float hi = __uint_as_float((unsigned)(acc0[i][jp] >> 32));
            hv[2 * jp]     = lo * invn + sm[SB_B + c0];
            hv[2 * jp + 1] = hi * invn + sm[SB_B + c0 + 1];
        }
        float s1 = 0.f;
        #pragma unroll
        for (int j = 0; j < 8; ++j) s1 += hv[j];
        s1 = wred(s1);
        float mu = s1 * (1.0f / 256.0f);
        float s2 = 0.f;
        #pragma unroll
        for (int j = 0; j < 8; ++j) { float d = hv[j] - mu; s2 += d * d; }
        s2 = wred(s2);
        float rstd = 1.0f / sqrtf(s2 * (1.0f / 256.0f) + 1e-5f);
        float zp[8];
        #pragma unroll
        for (int jp = 0; jp < 4; ++jp) {
            int c0 = 2 * tn + 64 * jp;
            zp[2 * jp]     = (hv[2 * jp] - mu) * rstd * sm[SB_G + c0] + sm[SB_BE + c0];
            zp[2 * jp + 1] = (hv[2 * jp + 1] - mu) * rstd * sm[SB_G + c0 + 1] + sm[SB_BE + c0 + 1];
        }
        float s3 = 0.f;
        #pragma unroll
        for (int j = 0; j < 8; ++j) s3 += zp[j] * zp[j];
        s3 = wred(s3);
        float zn = fmaxf(sqrtf(s3), 1e-12f);
        float szz = 0.f;
        #pragma unroll
        for (int jp = 0; jp < 4; ++jp) {
            int c0 = 2 * tn + 64 * jp;
            float2 zv = make_float2(zp[2 * jp] / zn, zp[2 * jp + 1] / zn);
            szz += zv.x * zv.x + zv.y * zv.y;
            *(float2*)&sm[ZS_OFF + lrow * P_DIM + c0] = zv;
        }
        szz = wred(szz);          // sum of ROUNDED z elements squared (mimics ref)
        if (tn == 0) sm[SB_ZZ + lrow] = szz;
    }
    __syncthreads();

    // ---- codebook dots: 4-way split accumulators (reduced rounding drift) ----
    float dq[4][4][2];   // [q][row i][code e]
    #pragma unroll
    for (int q = 0; q < 4; ++q)
        #pragma unroll
        for (int i = 0; i < 4; ++i) { dq[q][i][0] = 0.f; dq[q][i][1] = 0.f; }

    #pragma unroll 4
    for (int kb = 0; kb < P_DIM / 4; ++kb) {
        float4 za[4];
        #pragma unroll
        for (int i = 0; i < 4; ++i)
            za[i] = *(const float4*)&sm[ZS_OFF + (tm + 16 * i) * P_DIM + kb * 4];
        #pragma unroll
        for (int q = 0; q < 4; ++q) {
            float2 cw = *(const float2*)&sm[SB_CBT + (kb * 4 + q) * N_CODE + 2 * tn];
            #pragma unroll
            for (int i = 0; i < 4; ++i) {
                float zv = ((const float*)&za[i])[q];
                dq[q][i][0] += zv * cw.x;
                dq[q][i][1] += zv * cw.y;
            }
        }
    }

    // ---- argmin with reference-matching dist = (zz - 2*dot) + cn ----
    float cn0 = g_cbn2[2 * tn];
    float cn1 = g_cbn2[2 * tn + 1];
    float lpart = 0.f;
    #pragma unroll
    for (int i = 0; i < 4; ++i) {
        float dot0 = __fadd_rn(__fadd_rn(dq[0][i][0], dq[1][i][0]),
                               __fadd_rn(dq[2][i][0], dq[3][i][0]));
        float dot1 = __fadd_rn(__fadd_rn(dq[0][i][1], dq[1][i][1]),
                               __fadd_rn(dq[2][i][1], dq[3][i][1]));
        int lrow = tm + 16 * i;
        float zz = sm[SB_ZZ + lrow];
        float d0 = __fadd_rn(__fsub_rn(zz, 2.0f * dot0), cn0);
        float d1 = __fadd_rn(__fsub_rn(zz, 2.0f * dot1), cn1);
        float bd = d0; int bk = 2 * tn;
        if (d1 < bd) { bd = d1; bk = 2 * tn + 1; }
        #pragma unroll
        for (int o = 16; o; o >>= 1) {
            float od = __shfl_xor_sync(FULLMASK, bd, o);
            int   ok = __shfl_xor_sync(FULLMASK, bk, o);
            if (od < bd || (od == bd && ok < bk)) { bd = od; bk = ok; }
        }
        int grow = rowbase + lrow;
        const float* cbr = cb + bk * P_DIM;
        #pragma unroll
        for (int jp = 0; jp < 4; ++jp) {
            int c0 = 2 * tn + 64 * jp;
            float2 cv = *(const float2*)&cbr[c0];
            float2 zz2 = *(const float2*)&sm[ZS_OFF + lrow * P_DIM + c0];
            float e0 = cv.x - zz2.x, e1 = cv.y - zz2.y;
            lpart += e0 * e0 + e1 * e1;
            *(float2*)&out[(size_t)grow * P_DIM + c0] = cv;
        }
        if (tn == 0 && aux) out[IDX_OFF + grow] = (float)bk;
    }
    lpart = wred(lpart);
    if (tn == 0) atomicAdd(&sm[SB_LOSS], lpart);
    __syncthreads();
    if (tid == 0 && aux)
        atomicAdd(&out[LOSS_OFF], sm[SB_LOSS] * (0.25f / 16777216.0f));
}

extern "C" void kernel_launch(void* const* d_in, const int* in_sizes, int n_in,
                              void* d_out, int out_size) {
    const float* zf = (const float*)d_in[0];
    const float* Wm = (const float*)d_in[1];
    const float* bb = (const float*)d_in[2];
    const float* gg = (const float*)d_in[3];
    const float* be = (const float*)d_in[4];
    const float* cb = (const float*)d_in[5];
    float* out = (float*)d_out;

    cudaFuncSetAttribute(main_kernel, cudaFuncAttributeMaxDynamicSharedMemorySize, SMEM_BYTES);
    init_kernel<<<1, 64>>>(cb, out, out_size);
    main_kernel<<<B_ROWS / MT, NTHREADS, SMEM_BYTES>>>(zf, Wm, bb, gg, be, cb, out, out_size);
}

// round 11
// speedup vs baseline: 1.7959x; 1.7959x over previous
#include <cuda_runtime.h>
#include <cuda_bf16.h>
#include <cstdint>
#include <cstddef>

#define FULLMASK 0xffffffffu
#define B_ROWS 65536
#define D_INN 1408
#define P_DIM 256
#define N_CODE 64
#define KCH 32
#define NCH 44
#define NTHREADS 256

#define IDX_OFF  ((size_t)B_ROWS * P_DIM)
#define LOSS_OFF (IDX_OFF + B_ROWS)

// ---- smem byte offsets ----
#define SB_BIAS  0
#define SB_GAM   1024
#define SB_BET   2048
#define SB_NRM   3072      // float[128]
#define SB_ZZ    3584      // float[128]
#define SB_LOSSS 4096
#define UOFF     5120
#define ASTG(bf)  (UOFF + (bf) * 18432)                     // fp32 stage [2][128][36]
#define APL(bf,p) (UOFF + 36864 + (bf) * 16384 + (p) * 8192)  // A planes, tiled
#define BPL(bf,p) (UOFF + 69632 + (bf) * 32768 + (p) * 16384) // B planes, tiled
// epilogue overlays (HBUF overlaps GEMM bufs; CBT is beyond them)
#define HBUF     UOFF
#define HSTRIDE  260
#define CBT      (UOFF + 135168)
#define SMEM_BYTES (UOFF + 200704)   // 205824

#define PLSZ ((size_t)NCH * 16384)
__device__ unsigned char g_wtb[2 * NCH * 16384];   // W^T split planes, tiled+slotted
__device__ float g_cbn2[N_CODE];

static __device__ __forceinline__ unsigned smaddr(const void* p) {
    unsigned a;
    asm("{ .reg .u64 t; cvta.to.shared.u64 t, %1; cvt.u32.u64 %0, t; }" : "=r"(a) : "l"(p));
    return a;
}
static __device__ __forceinline__ void cp16(void* s, const void* g) {
    asm volatile("cp.async.cg.shared.global [%0], [%1], 16;\n" :: "r"(smaddr(s)), "l"(g));
}
static __device__ __forceinline__ float wred(float v) {
    #pragma unroll
    for (int o = 16; o; o >>= 1) v += __shfl_xor_sync(FULLMASK, v, o);
    return v;
}

#define LDSM4(d0, d1, d2, d3, addr) \
    asm volatile("ldmatrix.sync.aligned.m8n8.x4.shared.b16 {%0,%1,%2,%3}, [%4];" \
                 : "=r"(d0), "=r"(d1), "=r"(d2), "=r"(d3) : "r"(addr))

#define MMA16816(c, a, b0, b1) \
    asm volatile("mma.sync.aligned.m16n8k16.row.col.f32.bf16.bf16.f32 " \
                 "{%0,%1,%2,%3},{%4,%5,%6,%7},{%8,%9},{%0,%1,%2,%3};" \
                 : "+f"((c)[0]), "+f"((c)[1]), "+f"((c)[2]), "+f"((c)[3]) \
                 : "r"((a)[0]), "r"((a)[1]), "r"((a)[2]), "r"((a)[3]), "r"(b0), "r"(b1))

// ---- init: split W^T into 2 bf16 planes, tiled (128B 8x8 tiles) + slot-XOR ----
__global__ void init_w_kernel(const float* __restrict__ Wm) {
    int c = blockIdx.x >> 2, kb = blockIdx.x & 3, n = threadIdx.x;
    __align__(16) __nv_bfloat16 h8[8], m8[8];
    #pragma unroll
    for (int pos = 0; pos < 8; ++pos) {
        int k = c * KCH + kb * 8 + pos;
        float w = Wm[(size_t)k * P_DIM + n];
        __nv_bfloat16 h = __float2bfloat16_rn(w);
        __nv_bfloat16 m = __float2bfloat16_rn(w - __bfloat162float(h));
        h8[pos] = h; m8[pos] = m;
    }
    int nb = n >> 3;
    int tile = nb * 4 + kb;
    size_t off = (size_t)c * 16384 + tile * 128 + (((n & 7) ^ (tile & 7)) << 4);
    *(uint4*)(g_wtb + off)        = *(uint4*)h8;
    *(uint4*)(g_wtb + PLSZ + off) = *(uint4*)m8;
}

__global__ void init_misc_kernel(const float* __restrict__ cb, float* __restrict__ out, int out_size) {
    int k = threadIdx.x;
    if (k < N_CODE) {
        const float* r = cb + k * P_DIM;
        double s = 0.0;
        #pragma unroll 8
        for (int c = 0; c < P_DIM; ++c) { double v = (double)r[c]; s += v * v; }
        g_cbn2[k] = (float)s;
    }
    if (k == 0 && (size_t)out_size > LOSS_OFF) out[LOSS_OFF] = 0.f;
}

__global__ void __launch_bounds__(NTHREADS, 1)
main_kernel(const float* __restrict__ zf, const float* __restrict__ bb,
            const float* __restrict__ gg, const float* __restrict__ be,
            const float* __restrict__ cb, float* __restrict__ out, int out_size) {
    extern __shared__ char smem[];
    const int tid = threadIdx.x;
    const int lane = tid & 31;
    const int wid = tid >> 5;          // 0..7
    const int wr = wid >> 2;           // 0..1  (64-row group)
    const int wc = wid & 3;            // 0..3  (64-col group)
    const int rowbase = blockIdx.x * 128;
    const bool aux = (size_t)out_size > LOSS_OFF;
    const unsigned sbase = smaddr(smem);
    float* smf = (float*)smem;

    // ---- prefetch chunk 0 ----
    #pragma unroll
    for (int t = 0; t < 4; ++t) {          // A stage: 1024 x 16B
        int u = tid + t * NTHREADS;
        int r = u >> 3, j = u & 7;
        cp16(smem + ASTG(0) + r * 144 + j * 16,
             zf + (size_t)(rowbase + r) * D_INN + j * 4);
    }
    #pragma unroll
    for (int t = 0; t < 4; ++t) {          // B plane 0
        int u = tid + t * NTHREADS;
        cp16(smem + BPL(0, 0) + u * 16, g_wtb + (size_t)u * 16);
    }
    #pragma unroll
    for (int t = 0; t < 4; ++t) {          // B plane 1
        int u = tid + t * NTHREADS;
        cp16(smem + BPL(0, 1) + u * 16, g_wtb + PLSZ + (size_t)u * 16);
    }
    asm volatile("cp.async.commit_group;\n");

    // ---- params, loss, cbt (CBT region doesn't overlap GEMM bufs) ----
    smf[SB_BIAS / 4 + tid] = bb[tid];
    smf[SB_GAM  / 4 + tid] = gg[tid];
    smf[SB_BET  / 4 + tid] = be[tid];
    if (tid == 0) smf[SB_LOSSS / 4] = 0.f;
    float* cbt = (float*)(smem + CBT);
    #pragma unroll
    for (int t = 0; t < (N_CODE * P_DIM) / NTHREADS; ++t) {
        int i = tid + t * NTHREADS;
        int k = i >> 8, cc = i & 255;
        cbt[cc * N_CODE + k] = cb[i];
    }
    // ---- row L2 norms (2 lanes per row) ----
    {
        int r = tid >> 1, q = tid & 1;
        const float4* z4 = (const float4*)zf;
        size_t base = (size_t)(rowbase + r) * (D_INN / 4) + q;
        float s = 0.f;
        #pragma unroll 8
        for (int t = 0; t < D_INN / 8; ++t) {
            float4 v = z4[base + 2 * t];
            s += v.x * v.x + v.y * v.y + v.z * v.z + v.w * v.w;
        }
        s += __shfl_xor_sync(FULLMASK, s, 1);
        if (q == 0) smf[SB_NRM / 4 + r] = s;
    }

    // ---- GEMM: 128x256 per CTA, 3-term split on HMMA ----
    float acc[4][8][4];
    #pragma unroll
    for (int mt = 0; mt < 4; ++mt)
        #pragma unroll
        for (int nt = 0; nt < 8; ++nt)
            #pragma unroll
            for (int e = 0; e < 4; ++e) acc[mt][nt][e] = 0.f;

    for (int c = 0; c < NCH; ++c) {
        int bf = c & 1;
        // chunk c's loads complete; barrier also orders ALL warps' chunk-(c-1)
        // ldmatrix reads BEFORE the prefetch below overwrites buffer nb.
        asm volatile("cp.async.wait_group 0;\n");
        __syncthreads();
        if (c + 1 < NCH) {
            int nb = bf ^ 1;
            #pragma unroll
            for (int t = 0; t < 4; ++t) {
                int u = tid + t * NTHREADS;
                int r = u >> 3, j = u & 7;
                cp16(smem + ASTG(nb) + r * 144 + j * 16,
                     zf + (size_t)(rowbase + r) * D_INN + (c + 1) * KCH + j * 4);
            }
            #pragma unroll
            for (int t = 0; t < 4; ++t) {
                int u = tid + t * NTHREADS;
                cp16(smem + BPL(nb, 0) + u * 16, g_wtb + (size_t)(c + 1) * 16384 + u * 16);
            }
            #pragma unroll
            for (int t = 0; t < 4; ++t) {
                int u = tid + t * NTHREADS;
                cp16(smem + BPL(nb, 1) + u * 16, g_wtb + PLSZ + (size_t)(c + 1) * 16384 + u * 16);
            }
            asm volatile("cp.async.commit_group;\n");
        }

        // convert A fp32 -> 2 bf16 planes (tiled layout, conflict-free)
        const float* stg = (const float*)(smem + ASTG(bf));
        #pragma unroll
        for (int pass = 0; pass < 2; ++pass) {
            int r = pass * 64 + (wid << 3) + (lane & 7);
            int kb = lane >> 3;
            const float* srow = stg + r * 36 + kb * 8;
            float4 v0 = *(const float4*)srow;
            float4 v1 = *(const float4*)(srow + 4);
            float vv[8] = {v0.x, v0.y, v0.z, v0.w, v1.x, v1.y, v1.z, v1.w};
            __align__(16) __nv_bfloat16 h8[8], m8[8];
            #pragma unroll
            for (int j = 0; j < 8; ++j) {
                __nv_bfloat16 h = __float2bfloat16_rn(vv[j]);
                __nv_bfloat16 m = __float2bfloat16_rn(vv[j] - __bfloat162float(h));
                h8[j] = h; m8[j] = m;
            }
            int tile = ((r >> 3) << 2) + kb;
            unsigned off = tile * 128 + (((r & 7) ^ (tile & 7)) << 4);
            *(uint4*)(smem + APL(bf, 0) + off) = *(uint4*)h8;
            *(uint4*)(smem + APL(bf, 1) + off) = *(uint4*)m8;
        }
        __syncthreads();

        // MMA: terms A0*B0, A0*B1, A1*B0
        #pragma unroll
        for (int s = 0; s < 2; ++s) {
            int kb0 = 2 * s;
            int i4 = lane >> 3;
            unsigned bfr[2][16];
            #pragma unroll
            for (int p = 0; p < 2; ++p)
                #pragma unroll
                for (int j = 0; j < 4; ++j) {
                    int nb = wc * 8 + 2 * j + (i4 >> 1);
                    int kb = kb0 + (i4 & 1);
                    int tile = nb * 4 + kb;
                    unsigned addr = sbase + BPL(bf, p) + tile * 128 + (((lane & 7) ^ (tile & 7)) << 4);
                    LDSM4(bfr[p][j * 4 + 0], bfr[p][j * 4 + 1], bfr[p][j * 4 + 2], bfr[p][j * 4 + 3], addr);
                }
            unsigned afr[16];
            #pragma unroll
            for (int mt = 0; mt < 4; ++mt) {
                int rb = wr * 8 + mt * 2 + (i4 & 1);
                int kb = kb0 + (i4 >> 1);
                int tile = rb * 4 + kb;
                unsigned addr = sbase + APL(bf, 0) + tile * 128 + (((lane & 7) ^ (tile & 7)) << 4);
                LDSM4(afr[mt * 4 + 0], afr[mt * 4 + 1], afr[mt * 4 + 2], afr[mt * 4 + 3], addr);
            }
            #pragma unroll
            for (int mt = 0; mt < 4; ++mt)
                #pragma unroll
                for (int nt = 0; nt < 8; ++nt) {
                    int bi = (nt >> 1) * 4 + (nt & 1) * 2;
                    MMA16816(acc[mt][nt], &afr[mt * 4], bfr[0][bi], bfr[0][bi + 1]);
                    MMA16816(acc[mt][nt], &afr[mt * 4], bfr[1][bi], bfr[1][bi + 1]);
                }
            #pragma unroll
            for (int mt = 0; mt < 4; ++mt) {
                int rb = wr * 8 + mt * 2 + (i4 & 1);
                int kb = kb0 + (i4 >> 1);
                int tile = rb * 4 + kb;
                unsigned addr = sbase + APL(bf, 1) + tile * 128 + (((lane & 7) ^ (tile & 7)) << 4);
                LDSM4(afr[mt * 4 + 0], afr[mt * 4 + 1], afr[mt * 4 + 2], afr[mt * 4 + 3], addr);
            }
            #pragma unroll
            for (int mt = 0; mt < 4; ++mt)
                #pragma unroll
                for (int nt = 0; nt < 8; ++nt) {
                    int bi = (nt >> 1) * 4 + (nt & 1) * 2;
                    MMA16816(acc[mt][nt], &afr[mt * 4], bfr[0][bi], bfr[0][bi + 1]);
                }
        }
    }
    __syncthreads();   // GEMM buffers dead; HBUF overlay becomes writable

    // ---- h writeback: h = acc/||x|| + b ----
    float* hbuf = (float*)(smem + HBUF);
    #pragma unroll
    for (int mt = 0; mt < 4; ++mt) {
        int r1 = wr * 64 + mt * 16 + (lane >> 2);
        int r2 = r1 + 8;
        float invn1 = 1.0f / fmaxf(sqrtf(smf[SB_NRM / 4 + r1]), 1e-12f);
        float invn2 = 1.0f / fmaxf(sqrtf(smf[SB_NRM / 4 + r2]), 1e-12f);
        #pragma unroll
        for (int nt = 0; nt < 8; ++nt) {
            int c0 = wc * 64 + nt * 8 + 2 * (lane & 3);
            float2 o1 = make_float2(acc[mt][nt][0] * invn1 + smf[SB_BIAS / 4 + c0],
                                    acc[mt][nt][1] * invn1 + smf[SB_BIAS / 4 + c0 + 1]);
            float2 o2 = make_float2(acc[mt][nt][2] * invn2 + smf[SB_BIAS / 4 + c0],
                                    acc[mt][nt][3] * invn2 + smf[SB_BIAS / 4 + c0 + 1]);
            *(float2*)&hbuf[r1 * HSTRIDE + c0] = o1;
            *(float2*)&hbuf[r2 * HSTRIDE + c0] = o2;
        }
    }
    __syncthreads();

    // ---- LayerNorm + l2norm per row (8 warps x 16 rows) ----
    const int tn = lane;
    #pragma unroll
    for (int i = 0; i < 16; ++i) {
        int lrow = wid + 8 * i;
        float hv[8];
        #pragma unroll
        for (int jp = 0; jp < 4; ++jp) {
            int c0 = 2 * tn + 64 * jp;
            float2 v = *(const float2*)&hbuf[lrow * HSTRIDE + c0];
            hv[2 * jp] = v.x; hv[2 * jp + 1] = v.y;
        }
        float s1 = 0.f;
        #pragma unroll
        for (int j = 0; j < 8; ++j) s1 += hv[j];
        s1 = wred(s1);
        float mu = s1 * (1.0f / 256.0f);
        float s2 = 0.f;
        #pragma unroll
        for (int j = 0; j < 8; ++j) { float d = hv[j] - mu; s2 += d * d; }
        s2 = wred(s2);
        float rstd = 1.0f / sqrtf(s2 * (1.0f / 256.0f) + 1e-5f);
        float zp[8];
        #pragma unroll
        for (int jp = 0; jp < 4; ++jp) {
            int c0 = 2 * tn + 64 * jp;
            zp[2 * jp]     = (hv[2 * jp] - mu) * rstd * smf[SB_GAM / 4 + c0] + smf[SB_BET / 4 + c0];
            zp[2 * jp + 1] = (hv[2 * jp + 1] - mu) * rstd * smf[SB_GAM / 4 + c0 + 1] + smf[SB_BET / 4 + c0 + 1];
        }
        float s3 = 0.f;
        #pragma unroll
        for (int j = 0; j < 8; ++j) s3 += zp[j] * zp[j];
        s3 = wred(s3);
        float zn = fmaxf(sqrtf(s3), 1e-12f);
        float szz = 0.f;
        #pragma unroll
        for (int jp = 0; jp < 4; ++jp) {
            int c0 = 2 * tn + 64 * jp;
            float2 zv = make_float2(zp[2 * jp] / zn, zp[2 * jp + 1] / zn);
            szz += zv.x * zv.x + zv.y * zv.y;
            *(float2*)&hbuf[lrow * HSTRIDE + c0] = zv;
        }
        szz = wred(szz);
        if (tn == 0) smf[SB_ZZ / 4 + lrow] = szz;
    }
    __syncthreads();

    // ---- codebook dots + argmin + outputs (two passes of 8 rows per warp) ----
    float cn0 = g_cbn2[2 * tn];
    float cn1 = g_cbn2[2 * tn + 1];
    float lpart = 0.f;
    #pragma unroll
    for (int pp = 0; pp < 2; ++pp) {
        float dq[4][8][2];
        #pragma unroll
        for (int q = 0; q < 4; ++q)
            #pragma unroll
            for (int i = 0; i < 8; ++i) { dq[q][i][0] = 0.f; dq[q][i][1] = 0.f; }
        #pragma unroll 2
        for (int kb = 0; kb < P_DIM / 4; ++kb) {
            float4 za[8];
            #pragma unroll
            for (int i = 0; i < 8; ++i)
                za[i] = *(const float4*)&hbuf[(wid + 64 * pp + 8 * i) * HSTRIDE + kb * 4];
            #pragma unroll
            for (int q = 0; q < 4; ++q) {
                float2 cw = *(const float2*)&cbt[(kb * 4 + q) * N_CODE + 2 * tn];
                #pragma unroll
                for (int i = 0; i < 8; ++i) {
                    float zv = ((const float*)&za[i])[q];
                    dq[q][i][0] += zv * cw.x;
                    dq[q][i][1] += zv * cw.y;
                }
            }
        }
        #pragma unroll
        for (int i = 0; i < 8; ++i) {
            float dot0 = __fadd_rn(__fadd_rn(dq[0][i][0], dq[1][i][0]),
                                   __fadd_rn(dq[2][i][0], dq[3][i][0]));
            float dot1 = __fadd_rn(__fadd_rn(dq[0][i][1], dq[1][i][1]),
                                   __fadd_rn(dq[2][i][1], dq[3][i][1]));
            int lrow = wid + 64 * pp + 8 * i;
            float zz = smf[SB_ZZ / 4 + lrow];
            float d0 = __fadd_rn(__fsub_rn(zz, 2.0f * dot0), cn0);
            float d1 = __fadd_rn(__fsub_rn(zz, 2.0f * dot1), cn1);
            float bd = d0; int bk = 2 * tn;
            if (d1 < bd) { bd = d1; bk = 2 * tn + 1; }
            #pragma unroll
            for (int o = 16; o; o >>= 1) {
                float od = __shfl_xor_sync(FULLMASK, bd, o);
                int   ok = __shfl_xor_sync(FULLMASK, bk, o);
                if (od < bd || (od == bd && ok < bk)) { bd = od; bk = ok; }
            }
            int grow = rowbase + lrow;
            const float* cbr = cb + bk * P_DIM;
            #pragma unroll
            for (int jp = 0; jp < 4; ++jp) {
                int c0 = 2 * tn + 64 * jp;
                float2 cv = *(const float2*)&cbr[c0];
                float2 zz2 = *(const float2*)&hbuf[lrow * HSTRIDE + c0];
                float e0 = cv.x - zz2.x, e1 = cv.y - zz2.y;
                lpart += e0 * e0 + e1 * e1;
                *(float2*)&out[(size_t)grow * P_DIM + c0] = cv;
            }
            if (tn == 0 && aux) out[IDX_OFF + grow] = (float)bk;
        }
    }
    lpart = wred(lpart);
    if (tn == 0) atomicAdd(&smf[SB_LOSSS / 4], lpart);
    __syncthreads();
    if (tid == 0 && aux)
        atomicAdd(&out[LOSS_OFF], smf[SB_LOSSS / 4] * (0.25f / 16777216.0f));
}

extern "C" void kernel_launch(void* const* d_in, const int* in_sizes, int n_in,
                              void* d_out, int out_size) {
    const float* zf = (const float*)d_in[0];
    const float* Wm = (const float*)d_in[1];
    const float* bb = (const float*)d_in[2];
    const float* gg = (const float*)d_in[3];
    const float* be = (const float*)d_in[4];
    const float* cb = (const float*)d_in[5];
    float* out = (float*)d_out;

    cudaFuncSetAttribute(main_kernel, cudaFuncAttributeMaxDynamicSharedMemorySize, SMEM_BYTES);
    init_w_kernel<<<NCH * 4, P_DIM>>>(Wm);
    init_misc_kernel<<<1, 64>>>(cb, out, out_size);
    main_kernel<<<B_ROWS / 128, NTHREADS, SMEM_BYTES>>>(zf, bb, gg, be, cb, out, out_size);
}

// round 13
// speedup vs baseline: 2.1125x; 1.1763x over previous
#include <cuda_runtime.h>
#include <cuda_bf16.h>
#include <cstdint>
#include <cstddef>

#define FULLMASK 0xffffffffu
#define B_ROWS 65536
#define D_INN 1408
#define P_DIM 256
#define N_CODE 64
#define KCH 32
#define NCH 44
#define NTHREADS 512

#define IDX_OFF  ((size_t)B_ROWS * P_DIM)
#define LOSS_OFF (IDX_OFF + B_ROWS)

// ---- smem byte offsets ----
#define SB_BIAS  0
#define SB_GAM   1024
#define SB_BET   2048
#define SB_NRM   3072      // float[128]
#define SB_ZZ    3584      // float[128]
#define SB_LOSSS 4096
#define UOFF     5120
#define APL(p)    (UOFF + (p) * 8192)                        // A planes (single buf) 16KB
#define BPL(bf,p) (UOFF + 16384 + (bf) * 32768 + (p) * 16384) // B planes (double buf) 64KB
// epilogue overlays (HBUF overlaps GEMM bufs; CBT beyond them)
#define HBUF     UOFF
#define HSTRIDE  260
#define CBT      (UOFF + 133120)
#define SMEM_BYTES (UOFF + 198656)   // 203776

#define PLSZ ((size_t)NCH * 16384)
__device__ unsigned char g_wtb[2 * NCH * 16384];   // W^T split planes, tiled+slotted
__device__ float g_cbn2[N_CODE];

static __device__ __forceinline__ unsigned smaddr(const void* p) {
    unsigned a;
    asm("{ .reg .u64 t; cvta.to.shared.u64 t, %1; cvt.u32.u64 %0, t; }" : "=r"(a) : "l"(p));
    return a;
}
static __device__ __forceinline__ void cp16(void* s, const void* g) {
    asm volatile("cp.async.cg.shared.global [%0], [%1], 16;\n" :: "r"(smaddr(s)), "l"(g));
}
static __device__ __forceinline__ float wred(float v) {
    #pragma unroll
    for (int o = 16; o; o >>= 1) v += __shfl_xor_sync(FULLMASK, v, o);
    return v;
}

#define LDSM4(d0, d1, d2, d3, addr) \
    asm volatile("ldmatrix.sync.aligned.m8n8.x4.shared.b16 {%0,%1,%2,%3}, [%4];" \
                 : "=r"(d0), "=r"(d1), "=r"(d2), "=r"(d3) : "r"(addr))

#define MMA16816(c, a, b0, b1) \
    asm volatile("mma.sync.aligned.m16n8k16.row.col.f32.bf16.bf16.f32 " \
                 "{%0,%1,%2,%3},{%4,%5,%6,%7},{%8,%9},{%0,%1,%2,%3};" \
                 : "+f"((c)[0]), "+f"((c)[1]), "+f"((c)[2]), "+f"((c)[3]) \
                 : "r"((a)[0]), "r"((a)[1]), "r"((a)[2]), "r"((a)[3]), "r"(b0), "r"(b1))

// ---- init: split W^T into 2 bf16 planes, tiled (128B 8x8 tiles) + slot-XOR ----
__global__ void init_w_kernel(const float* __restrict__ Wm) {
    int c = blockIdx.x >> 2, kb = blockIdx.x & 3, n = threadIdx.x;
    __align__(16) __nv_bfloat16 h8[8], m8[8];
    #pragma unroll
    for (int pos = 0; pos < 8; ++pos) {
        int k = c * KCH + kb * 8 + pos;
        float w = Wm[(size_t)k * P_DIM + n];
        __nv_bfloat16 h = __float2bfloat16_rn(w);
        __nv_bfloat16 m = __float2bfloat16_rn(w - __bfloat162float(h));
        h8[pos] = h; m8[pos] = m;
    }
    int nb = n >> 3;
    int tile = nb * 4 + kb;
    size_t off = (size_t)c * 16384 + tile * 128 + (((n & 7) ^ (tile & 7)) << 4);
    *(uint4*)(g_wtb + off)        = *(uint4*)h8;
    *(uint4*)(g_wtb + PLSZ + off) = *(uint4*)m8;
}

__global__ void init_misc_kernel(const float* __restrict__ cb, float* __restrict__ out, int out_size) {
    int k = threadIdx.x;
    if (k < N_CODE) {
        const float* r = cb + k * P_DIM;
        double s = 0.0;
        #pragma unroll 8
        for (int c = 0; c < P_DIM; ++c) { double v = (double)r[c]; s += v * v; }
        g_cbn2[k] = (float)s;
    }
    if (k == 0 && (size_t)out_size > LOSS_OFF) out[LOSS_OFF] = 0.f;
}

__global__ void __launch_bounds__(NTHREADS, 1)
main_kernel(const float* __restrict__ zf, const float* __restrict__ bb,
            const float* __restrict__ gg, const float* __restrict__ be,
            const float* __restrict__ cb, float* __restrict__ out, int out_size) {
    extern __shared__ char smem[];
    const int tid = threadIdx.x;
    const int lane = tid & 31;
    const int wid = tid >> 5;          // 0..15
    const int wr = wid >> 2;           // 0..3  (32-row group)
    const int wc = wid & 3;            // 0..3  (64-col group)
    const int rowbase = blockIdx.x * 128;
    const bool aux = (size_t)out_size > LOSS_OFF;
    const unsigned sbase = smaddr(smem);
    float* smf = (float*)smem;

    // A-register mapping: each thread owns row arow, k-segment aseg (8 floats/chunk)
    const int arow = tid >> 2;
    const int aseg = tid & 3;
    const float* arow_ptr = zf + (size_t)(rowbase + arow) * D_INN + aseg * 8;

    // ---- prologue: A chunk 0 into regs, B chunk 0 via cp.async ----
    float4 a0 = *(const float4*)arow_ptr;
    float4 a1 = *(const float4*)(arow_ptr + 4);
    #pragma unroll
    for (int t = 0; t < 2; ++t) {          // B plane 0 (1024 x 16B)
        int u = tid + t * NTHREADS;
        cp16(smem + BPL(0, 0) + u * 16, g_wtb + (size_t)u * 16);
    }
    #pragma unroll
    for (int t = 0; t < 2; ++t) {          // B plane 1
        int u = tid + t * NTHREADS;
        cp16(smem + BPL(0, 1) + u * 16, g_wtb + PLSZ + (size_t)u * 16);
    }
    asm volatile("cp.async.commit_group;\n");

    // ---- params, loss, cbt (CBT region beyond GEMM bufs) ----
    if (tid < P_DIM) {
        smf[SB_BIAS / 4 + tid] = bb[tid];
        smf[SB_GAM  / 4 + tid] = gg[tid];
        smf[SB_BET  / 4 + tid] = be[tid];
    }
    if (tid == 0) smf[SB_LOSSS / 4] = 0.f;
    float* cbt = (float*)(smem + CBT);
    #pragma unroll
    for (int t = 0; t < (N_CODE * P_DIM) / NTHREADS; ++t) {
        int i = tid + t * NTHREADS;
        int k = i >> 8, cc = i & 255;
        cbt[cc * N_CODE + k] = cb[i];
    }

    // ---- GEMM: 128x256 per CTA, 16 warps, warp tile 32x64, 3-term split ----
    float acc[2][8][4];
    #pragma unroll
    for (int mt = 0; mt < 2; ++mt)
        #pragma unroll
        for (int nt = 0; nt < 8; ++nt)
            #pragma unroll
            for (int e = 0; e < 4; ++e) acc[mt][nt][e] = 0.f;
    float nacc = 0.f;   // row-norm partial (this thread's 8-wide segments)

    const int atile = (arow >> 3) * 4 + aseg;
    const unsigned aoff = atile * 128 + (((arow & 7) ^ (atile & 7)) << 4);

    for (int c = 0; c < NCH; ++c) {
        int bf = c & 1;
        // B(c) complete; barrier also orders chunk-(c-1) ldmatrix reads of
        // APL and BPL(nb) before they get overwritten below.
        asm volatile("cp.async.wait_group 0;\n");
        __syncthreads();
        if (c + 1 < NCH) {
            int nb = bf ^ 1;
            #pragma unroll
            for (int t = 0; t < 2; ++t) {
                int u = tid + t * NTHREADS;
                cp16(smem + BPL(nb, 0) + u * 16, g_wtb + (size_t)(c + 1) * 16384 + u * 16);
            }
            #pragma unroll
            for (int t = 0; t < 2; ++t) {
                int u = tid + t * NTHREADS;
                cp16(smem + BPL(nb, 1) + u * 16, g_wtb + PLSZ + (size_t)(c + 1) * 16384 + u * 16);
            }
            asm volatile("cp.async.commit_group;\n");
        }

        // convert A regs -> 2 bf16 planes; accumulate row norms
        {
            float vv[8] = {a0.x, a0.y, a0.z, a0.w, a1.x, a1.y, a1.z, a1.w};
            __align__(16) __nv_bfloat16 h8[8], m8[8];
            #pragma unroll
            for (int j = 0; j < 8; ++j) {
                nacc += vv[j] * vv[j];
                __nv_bfloat16 h = __float2bfloat16_rn(vv[j]);
                __nv_bfloat16 m = __float2bfloat16_rn(vv[j] - __bfloat162float(h));
                h8[j] = h; m8[j] = m;
            }
            *(uint4*)(smem + APL(0) + aoff) = *(uint4*)h8;
            *(uint4*)(smem + APL(1) + aoff) = *(uint4*)m8;
        }
        // issue A LDG for next chunk (lands during MMA below)
        if (c + 1 < NCH) {
            const float* p = arow_ptr + (c + 1) * KCH;
            a0 = *(const float4*)p;
            a1 = *(const float4*)(p + 4);
        }
        __syncthreads();

        // MMA: terms A0*B0, A0*B1, A1*B0
        #pragma unroll
        for (int s = 0; s < 2; ++s) {
            int kb0 = 2 * s;
            int i4 = lane >> 3;
            unsigned bfr[2][16];
            #pragma unroll
            for (int p = 0; p < 2; ++p)
                #pragma unroll
                for (int j = 0; j < 4; ++j) {
                    int nb = wc * 8 + 2 * j + (i4 >> 1);
                    int kb = kb0 + (i4 & 1);
                    int tile = nb * 4 + kb;
                    unsigned addr = sbase + BPL(bf, p) + tile * 128 + (((lane & 7) ^ (tile & 7)) << 4);
                    LDSM4(bfr[p][j * 4 + 0], bfr[p][j * 4 + 1], bfr[p][j * 4 + 2], bfr[p][j * 4 + 3], addr);
                }
            unsigned afr[8];
            #pragma unroll
            for (int mt = 0; mt < 2; ++mt) {
                int rb = wr * 4 + mt * 2 + (i4 & 1);
                int kb = kb0 + (i4 >> 1);
                int tile = rb * 4 + kb;
                unsigned addr = sbase + APL(0) + tile * 128 + (((lane & 7) ^ (tile & 7)) << 4);
                LDSM4(afr[mt * 4 + 0], afr[mt * 4 + 1], afr[mt * 4 + 2], afr[mt * 4 + 3], addr);
            }
            #pragma unroll
            for (int mt = 0; mt < 2; ++mt)
                #pragma unroll
                for (int nt = 0; nt < 8; ++nt) {
                    int bi = (nt >> 1) * 4 + (nt & 1) * 2;
                    MMA16816(acc[mt][nt], &afr[mt * 4], bfr[0][bi], bfr[0][bi + 1]);
                    MMA16816(acc[mt][nt], &afr[mt * 4], bfr[1][bi], bfr[1][bi + 1]);
                }
            #pragma unroll
            for (int mt = 0; mt < 2; ++mt) {
                int rb = wr * 4 + mt * 2 + (i4 & 1);
                int kb = kb0 + (i4 >> 1);
                int tile = rb * 4 + kb;
                unsigned addr = sbase + APL(1) + tile * 128 + (((lane & 7) ^ (tile & 7)) << 4);
                LDSM4(afr[mt * 4 + 0], afr[mt * 4 + 1], afr[mt * 4 + 2], afr[mt * 4 + 3], addr);
            }
            #pragma unroll
            for (int mt = 0; mt < 2; ++mt)
                #pragma unroll
                for (int nt = 0; nt < 8; ++nt) {
                    int bi = (nt >> 1) * 4 + (nt & 1) * 2;
                    MMA16816(acc[mt][nt], &afr[mt * 4], bfr[0][bi], bfr[0][bi + 1]);
                }
        }
    }

    // ---- finalize row norms (4 threads per row share arow) ----
    nacc += __shfl_xor_sync(FULLMASK, nacc, 1);
    nacc += __shfl_xor_sync(FULLMASK, nacc, 2);
    if (aseg == 0) smf[SB_NRM / 4 + arow] = nacc;
    __syncthreads();   // GEMM buffers dead; HBUF overlay writable; norms visible

    // ---- h writeback: h = acc/||x|| + b ----
    float* hbuf = (float*)(smem + HBUF);
    #pragma unroll
    for (int mt = 0; mt < 2; ++mt) {
        int r1 = wr * 32 + mt * 16 + (lane >> 2);
        int r2 = r1 + 8;
        float invn1 = 1.0f / fmaxf(sqrtf(smf[SB_NRM / 4 + r1]), 1e-12f);
        float invn2 = 1.0f / fmaxf(sqrtf(smf[SB_NRM / 4 + r2]), 1e-12f);
        #pragma unroll
        for (int nt = 0; nt < 8; ++nt) {
            int c0 = wc * 64 + nt * 8 + 2 * (lane & 3);
            float2 o1 = make_float2(acc[mt][nt][0] * invn1 + smf[SB_BIAS / 4 + c0],
                                    acc[mt][nt][1] * invn1 + smf[SB_BIAS / 4 + c0 + 1]);
            float2 o2 = make_float2(acc[mt][nt][2] * invn2 + smf[SB_BIAS / 4 + c0],
                                    acc[mt][nt][3] * invn2 + smf[SB_BIAS / 4 + c0 + 1]);
            *(float2*)&hbuf[r1 * HSTRIDE + c0] = o1;
            *(float2*)&hbuf[r2 * HSTRIDE + c0] = o2;
        }
    }
    __syncthreads();

    // ---- LayerNorm + l2norm per row (16 warps x 8 rows) ----
    const int tn = lane;
    #pragma unroll
    for (int i = 0; i < 8; ++i) {
        int lrow = wid + 16 * i;
        float hv[8];
        #pragma unroll
        for (int jp = 0; jp < 4; ++jp) {
            int c0 = 2 * tn + 64 * jp;
            float2 v = *(const float2*)&hbuf[lrow * HSTRIDE + c0];
            hv[2 * jp] = v.x; hv[2 * jp + 1] = v.y;
        }
        float s1 = 0.f;
        #pragma unroll
        for (int j = 0; j < 8; ++j) s1 += hv[j];
        s1 = wred(s1);
        float mu = s1 * (1.0f / 256.0f);
        float s2 = 0.f;
        #pragma unroll
        for (int j = 0; j < 8; ++j) { float d = hv[j] - mu; s2 += d * d; }
        s2 = wred(s2);
        float rstd = 1.0f / sqrtf(s2 * (1.0f / 256.0f) + 1e-5f);
        float zp[8];
        #pragma unroll
        for (int jp = 0; jp < 4; ++jp) {
            int c0 = 2 * tn + 64 * jp;
            zp[2 * jp]     = (hv[2 * jp] - mu) * rstd * smf[SB_GAM / 4 + c0] + smf[SB_BET / 4 + c0];
            zp[2 * jp + 1] = (hv[2 * jp + 1] - mu) * rstd * smf[SB_GAM / 4 + c0 + 1] + smf[SB_BET / 4 + c0 + 1];
        }
        float s3 = 0.f;
        #pragma unroll
        for (int j = 0; j < 8; ++j) s3 += zp[j] * zp[j];
        s3 = wred(s3);
        float zn = fmaxf(sqrtf(s3), 1e-12f);
        float szz = 0.f;
        #pragma unroll
        for (int jp = 0; jp < 4; ++jp) {
            int c0 = 2 * tn + 64 * jp;
            float2 zv = make_float2(zp[2 * jp] / zn, zp[2 * jp + 1] / zn);
            szz += zv.x * zv.x + zv.y * zv.y;
            *(float2*)&hbuf[lrow * HSTRIDE + c0] = zv;
        }
        szz = wred(szz);
        if (tn == 0) smf[SB_ZZ / 4 + lrow] = szz;
    }
    __syncthreads();

    // ---- codebook dots + argmin + outputs (16 warps x 8 rows) ----
    float cn0 = g_cbn2[2 * tn];
    float cn1 = g_cbn2[2 * tn + 1];
    float lpart = 0.f;
    {
        float dq[4][8][2];
        #pragma unroll
        for (int q = 0; q < 4; ++q)
            #pragma unroll
            for (int i = 0; i < 8; ++i) { dq[q][i][0] = 0.f; dq[q][i][1] = 0.f; }
        #pragma unroll 2
        for (int kb = 0; kb < P_DIM / 4; ++kb) {
            float4 za[8];
            #pragma unroll
            for (int i = 0; i < 8; ++i)
                za[i] = *(const float4*)&hbuf[(wid + 16 * i) * HSTRIDE + kb * 4];
            #pragma unroll
            for (int q = 0; q < 4; ++q) {
                float2 cw = *(const float2*)&cbt[(kb * 4 + q) * N_CODE + 2 * tn];
                #pragma unroll
                for (int i = 0; i < 8; ++i) {
                    float zv = ((const float*)&za[i])[q];
                    dq[q][i][0] += zv * cw.x;
                    dq[q][i][1] += zv * cw.y;
                }
            }
        }
        #pragma unroll
        for (int i = 0; i < 8; ++i) {
            float dot0 = __fadd_rn(__fadd_rn(dq[0][i][0], dq[1][i][0]),
                                   __fadd_rn(dq[2][i][0], dq[3][i][0]));
            float dot1 = __fadd_rn(__fadd_rn(dq[0][i][1], dq[1][i][1]),
                                   __fadd_rn(dq[2][i][1], dq[3][i][1]));
            int lrow = wid + 16 * i;
            float zz = smf[SB_ZZ / 4 + lrow];
            float d0 = __fadd_rn(__fsub_rn(zz, 2.0f * dot0), cn0);
            float d1 = __fadd_rn(__fsub_rn(zz, 2.0f * dot1), cn1);
            float bd = d0; int bk = 2 * tn;
            if (d1 < bd) { bd = d1; bk = 2 * tn + 1; }
            #pragma unroll
            for (int o = 16; o; o >>= 1) {
                float od = __shfl_xor_sync(FULLMASK, bd, o);
                int   ok = __shfl_xor_sync(FULLMASK, bk, o);
                if (od < bd || (od == bd && ok < bk)) { bd = od; bk = ok; }
            }
            int grow = rowbase + lrow;
            const float* cbr = cb + bk * P_DIM;
            #pragma unroll
            for (int jp = 0; jp < 4; ++jp) {
                int c0 = 2 * tn + 64 * jp;
                float2 cv = *(const float2*)&cbr[c0];
                float2 zz2 = *(const float2*)&hbuf[lrow * HSTRIDE + c0];
                float e0 = cv.x - zz2.x, e1 = cv.y - zz2.y;
                lpart += e0 * e0 + e1 * e1;
                *(float2*)&out[(size_t)grow * P_DIM + c0] = cv;
            }
            if (tn == 0 && aux) out[IDX_OFF + grow] = (float)bk;
        }
    }
    lpart = wred(lpart);
    if (tn == 0) atomicAdd(&smf[SB_LOSSS / 4], lpart);
    __syncthreads();
    if (tid == 0 && aux)
        atomicAdd(&out[LOSS_OFF], smf[SB_LOSSS / 4] * (0.25f / 16777216.0f));
}

extern "C" void kernel_launch(void* const* d_in, const int* in_sizes, int n_in,
                              void* d_out, int out_size) {
    const float* zf = (const float*)d_in[0];
    const float* Wm = (const float*)d_in[1];
    const float* bb = (const float*)d_in[2];
    const float* gg = (const float*)d_in[3];
    const float* be = (const float*)d_in[4];
    const float* cb = (const float*)d_in[5];
    float* out = (float*)d_out;

    cudaFuncSetAttribute(main_kernel, cudaFuncAttributeMaxDynamicSharedMemorySize, SMEM_BYTES);
    init_w_kernel<<<NCH * 4, P_DIM>>>(Wm);
    init_misc_kernel<<<1, 64>>>(cb, out, out_size);
    main_kernel<<<B_ROWS / 128, NTHREADS, SMEM_BYTES>>>(zf, bb, gg, be, cb, out, out_size);
}